// round 13
// baseline (speedup 1.0000x reference)
#include <cuda_runtime.h>
#include <cuda_fp16.h>
#include <cstdint>

#define BOND_D 128
#define MAXN   100000
#define MAXE   500000
#define NHEAD  4

// Pd[head][n][128] fp16: x@W_top + bias (dst side). 102.4 MB
__device__ __align__(16) __half g_Pd[(size_t)NHEAD * MAXN * BOND_D];
// Q[head][n][256] fp16, quad q: halves [8q..8q+4) = Pj cols 4q..4q+3 (src side),
//                               halves [8q+4..8q+8) = x_j cols 4q..4q+3.
__device__ __align__(16) __half g_Q[(size_t)NHEAD * MAXN * 256];

// CSR scratch (key k = head*N + dst):
__device__ int g_cnt[NHEAD * MAXN];       // segment degree
__device__ int g_off[NHEAD * MAXN];       // exclusive-scan start offset
__device__ int g_cur[NHEAD * MAXN];       // scatter cursor
__device__ int g_srcs[NHEAD * MAXE];      // src per edge, grouped by (head,dst)
__device__ int g_part[512];               // scan partials

__device__ int g_idx_is64;                // 1 if edge_index is int64, 0 if int32

// ---------------------------------------------------------------------------
// Kernel 0: detect edge_index dtype. int64 indices in [0,N) all pass; int32
// data read as int64 = lo + hi*2^32 fails immediately. Deterministic.
// ---------------------------------------------------------------------------
__global__ void detect_idx_kernel(const long long* __restrict__ ei, int N)
{
    __shared__ int bad;
    if (threadIdx.x == 0) bad = 0;
    __syncthreads();
#pragma unroll
    for (int k = 0; k < 4; k++) {
        long long v = ei[threadIdx.x + k * 256];
        if (v < 0 || v >= N) bad = 1;
    }
    __syncthreads();
    if (threadIdx.x == 0) g_idx_is64 = !bad;
}

// ---------------------------------------------------------------------------
// Kernel 1: fused precompute (fp16 ldmatrix + m16n8k16) — unchanged (R10).
// ---------------------------------------------------------------------------
#define SWROW_U32 68
#define SW_U32   (128 * SWROW_U32)
#define SB_U32   (32 * SWROW_U32)
#define SP_U32   (32 * SWROW_U32)
#define SMEM_U32 (SW_U32 + SB_U32 + SP_U32 + 128)

__global__ __launch_bounds__(256) void precompute_kernel(
    const float* __restrict__ bond,
    const float* __restrict__ W,
    const float* __restrict__ bias,
    int N, int GX)
{
    extern __shared__ uint32_t smem_u[];
    uint32_t* sWu = smem_u;                 // [128][68] half2
    uint32_t* sBu = sWu + SW_U32;           // [32][68]  half2
    uint32_t* sPu = sBu + SB_U32;           // [32][68]  half2
    float*  sBias = (float*)(sPu + SP_U32); // [128]

    const int g    = blockIdx.y;
    const int head = g >> 1;
    const int half = g & 1;
    const float* Wg = W + ((size_t)head * 256 + (size_t)half * 128) * 128;

    for (int i = threadIdx.x; i < 128 * 32; i += blockDim.x) {
        const int row = i >> 5, c4 = (i & 31) * 4;
        const float4 v = *(const float4*)(Wg + (size_t)row * 128 + c4);
        const __half2 h0 = __floats2half2_rn(v.x, v.y);
        const __half2 h1 = __floats2half2_rn(v.z, v.w);
        uint32_t* d = sWu + row * SWROW_U32 + (c4 >> 1);
        d[0] = *(const uint32_t*)&h0;
        d[1] = *(const uint32_t*)&h1;
    }
    if (threadIdx.x < 128) sBias[threadIdx.x] = bias[head * 128 + threadIdx.x];

    const int warp   = threadIdx.x >> 5;
    const int lane   = threadIdx.x & 31;
    const int rowgrp = warp >> 2;
    const int colgrp = warp & 3;
    const int gid  = lane >> 2;
    const int tig  = lane & 3;

    const int lr  = lane & 7;
    const int mat = lane >> 3;
    const int a_row  = rowgrp * 16 + lr + ((mat & 1) << 3);
    const int a_kofs = (mat >> 1) << 3;
    const int b_krow = lr + ((mat & 1) << 3);
    const int b_nofs = colgrp * 32 + ((mat >> 1) << 3);

    const uint32_t sB_base = (uint32_t)__cvta_generic_to_shared(sBu);
    const uint32_t sW_base = (uint32_t)__cvta_generic_to_shared(sWu);
    const uint32_t aAddr0 = sB_base + (uint32_t)(a_row * 136 + a_kofs) * 2;
    const uint32_t bAddr0 = sW_base + (uint32_t)(b_krow * 136 + b_nofs) * 2;

    const int n_tiles = (N + 31) / 32;

    for (int tile = blockIdx.x; tile < n_tiles; tile += GX) {
        __syncthreads();

        for (int i = threadIdx.x; i < 32 * 32; i += blockDim.x) {
            const int row = i >> 5, c4 = (i & 31) * 4;
            int grow = tile * 32 + row;
            if (grow >= N) grow = N - 1;
            const float4 v = *(const float4*)(bond + (size_t)grow * 128 + c4);
            const __half2 h0 = __floats2half2_rn(v.x, v.y);
            const __half2 h1 = __floats2half2_rn(v.z, v.w);
            uint32_t* d = sBu + row * SWROW_U32 + (c4 >> 1);
            d[0] = *(const uint32_t*)&h0;
            d[1] = *(const uint32_t*)&h1;
        }
        __syncthreads();

        float acc[4][4];
#pragma unroll
        for (int nc = 0; nc < 4; nc++) {
            acc[nc][0] = 0.f; acc[nc][1] = 0.f; acc[nc][2] = 0.f; acc[nc][3] = 0.f;
        }

#pragma unroll
        for (int kc = 0; kc < 8; kc++) {
            uint32_t a0, a1, a2, a3;
            asm volatile(
                "ldmatrix.sync.aligned.m8n8.x4.shared.b16 {%0,%1,%2,%3}, [%4];"
                : "=r"(a0), "=r"(a1), "=r"(a2), "=r"(a3)
                : "r"(aAddr0 + kc * 32));
#pragma unroll
            for (int pair = 0; pair < 2; pair++) {
                uint32_t b0, b1, b2, b3;
                asm volatile(
                    "ldmatrix.sync.aligned.m8n8.x4.trans.shared.b16 "
                    "{%0,%1,%2,%3}, [%4];"
                    : "=r"(b0), "=r"(b1), "=r"(b2), "=r"(b3)
                    : "r"(bAddr0 + pair * 32 + kc * 16 * 272));
                const int nc = pair * 2;
                asm volatile(
                    "mma.sync.aligned.m16n8k16.row.col.f32.f16.f16.f32 "
                    "{%0,%1,%2,%3}, {%4,%5,%6,%7}, {%8,%9}, {%0,%1,%2,%3};"
                    : "+f"(acc[nc][0]), "+f"(acc[nc][1]),
                      "+f"(acc[nc][2]), "+f"(acc[nc][3])
                    : "r"(a0), "r"(a1), "r"(a2), "r"(a3), "r"(b0), "r"(b1));
                asm volatile(
                    "mma.sync.aligned.m16n8k16.row.col.f32.f16.f16.f32 "
                    "{%0,%1,%2,%3}, {%4,%5,%6,%7}, {%8,%9}, {%0,%1,%2,%3};"
                    : "+f"(acc[nc + 1][0]), "+f"(acc[nc + 1][1]),
                      "+f"(acc[nc + 1][2]), "+f"(acc[nc + 1][3])
                    : "r"(a0), "r"(a1), "r"(a2), "r"(a3), "r"(b2), "r"(b3));
            }
        }

        const int tr0 = rowgrp * 16 + gid;
        const int tr1 = tr0 + 8;
#pragma unroll
        for (int nc = 0; nc < 4; nc++) {
            const int c0 = colgrp * 32 + nc * 8 + tig * 2;
            float bx = 0.f, by = 0.f;
            if (half == 0) { bx = sBias[c0]; by = sBias[c0 + 1]; }
            const __half2 h0 = __floats2half2_rn(acc[nc][0] + bx, acc[nc][1] + by);
            const __half2 h1 = __floats2half2_rn(acc[nc][2] + bx, acc[nc][3] + by);
            sPu[tr0 * SWROW_U32 + (c0 >> 1)] = *(const uint32_t*)&h0;
            sPu[tr1 * SWROW_U32 + (c0 >> 1)] = *(const uint32_t*)&h1;
        }
        __syncthreads();

        if (half == 0) {
            __half* Pg = g_Pd + (size_t)head * N * 128;
#pragma unroll
            for (int it = 0; it < 2; it++) {
                const int idx = threadIdx.x + it * 256;
                const int row = idx >> 4, g8 = idx & 15;
                const int grow = tile * 32 + row;
                if (grow < N) {
                    const uint32_t* p = sPu + row * SWROW_U32 + g8 * 4;
                    uint4 v; v.x = p[0]; v.y = p[1]; v.z = p[2]; v.w = p[3];
                    *(uint4*)(Pg + (size_t)grow * 128 + g8 * 8) = v;
                }
            }
        } else {
            __half* Qg = g_Q + (size_t)head * N * 256;
#pragma unroll
            for (int it = 0; it < 4; it++) {
                const int idx = threadIdx.x + it * 256;
                const int row = idx >> 5, q = idx & 31;
                const int grow = tile * 32 + row;
                if (grow < N) {
                    const uint32_t* p = sPu + row * SWROW_U32 + q * 2;
                    const uint32_t* x = sBu + row * SWROW_U32 + q * 2;
                    uint4 v;
                    v.x = p[0]; v.y = p[1];
                    v.z = x[0]; v.w = x[1];
                    *(uint4*)(Qg + (size_t)grow * 256 + q * 8) = v;
                }
            }
        }
    }
}

// ---------------------------------------------------------------------------
// CSR build kernels (unchanged)
// ---------------------------------------------------------------------------
__global__ void csr_zero_kernel(int M)
{
    const int i = blockIdx.x * blockDim.x + threadIdx.x;
    if (i < M) { g_cnt[i] = 0; g_cur[i] = 0; }
}

__global__ void hist_kernel(const void* __restrict__ ei_raw, int N, int E)
{
    const int e = blockIdx.x * blockDim.x + threadIdx.x;
    const int head = blockIdx.y;
    if (e >= E) return;
    int dst;
    if (g_idx_is64) dst = (int)((const long long*)ei_raw)[(size_t)head * 2 * E + E + e];
    else            dst = ((const int*)ei_raw)[(size_t)head * 2 * E + E + e];
    dst = min(max(dst, 0), N - 1);
    atomicAdd(&g_cnt[head * N + dst], 1);
}

__global__ void scanA_kernel(int M)
{
    __shared__ int sh[256];
    const int tid = threadIdx.x;
    const int base = blockIdx.x * 1024 + tid * 4;
    int s = 0;
#pragma unroll
    for (int k = 0; k < 4; k++) if (base + k < M) s += g_cnt[base + k];
    sh[tid] = s; __syncthreads();
    for (int o = 128; o > 0; o >>= 1) {
        if (tid < o) sh[tid] += sh[tid + o];
        __syncthreads();
    }
    if (tid == 0) g_part[blockIdx.x] = sh[0];
}

__global__ void scanB_kernel(int P)
{
    __shared__ int sh[512];
    const int tid = threadIdx.x;
    const int v = (tid < P) ? g_part[tid] : 0;
    sh[tid] = v; __syncthreads();
    for (int o = 1; o < 512; o <<= 1) {
        const int t = (tid >= o) ? sh[tid - o] : 0;
        __syncthreads();
        sh[tid] += t;
        __syncthreads();
    }
    if (tid < P) g_part[tid] = sh[tid] - v;   // exclusive
}

__global__ void scanC_kernel(int M)
{
    __shared__ int sh[256];
    const int tid = threadIdx.x;
    const int base = blockIdx.x * 1024 + tid * 4;
    int v[4], e[4], s = 0;
#pragma unroll
    for (int k = 0; k < 4; k++) v[k] = (base + k < M) ? g_cnt[base + k] : 0;
#pragma unroll
    for (int k = 0; k < 4; k++) { e[k] = s; s += v[k]; }
    sh[tid] = s; __syncthreads();
    const int mine = s;
    for (int o = 1; o < 256; o <<= 1) {
        const int t = (tid >= o) ? sh[tid - o] : 0;
        __syncthreads();
        sh[tid] += t;
        __syncthreads();
    }
    const int pre = g_part[blockIdx.x] + sh[tid] - mine;
#pragma unroll
    for (int k = 0; k < 4; k++) if (base + k < M) g_off[base + k] = pre + e[k];
}

__global__ void scatter_kernel(const void* __restrict__ ei_raw, int N, int E)
{
    const int e = blockIdx.x * blockDim.x + threadIdx.x;
    const int head = blockIdx.y;
    if (e >= E) return;
    int src, dst;
    if (g_idx_is64) {
        const long long* eh = (const long long*)ei_raw + (size_t)head * 2 * E;
        src = (int)eh[e];
        dst = (int)eh[E + e];
    } else {
        const int* eh = (const int*)ei_raw + (size_t)head * 2 * E;
        src = eh[e];
        dst = eh[E + e];
    }
    src = min(max(src, 0), N - 1);
    dst = min(max(dst, 0), N - 1);
    const int k = head * N + dst;
    const int pos = g_off[k] + atomicAdd(&g_cur[k], 1);
    g_srcs[pos] = src;
}

// ---------------------------------------------------------------------------
// Kernel 3: dst-major gather v2. One warp per (head, dst).
//   8-wide chunks: 8 independent broadcast src loads, then 8 independent
//   uint4 Q loads in flight, then math. Deep MLP to hide L2 latency.
// ---------------------------------------------------------------------------
__device__ __forceinline__ float tanh_ap(float x)
{
    float y;
    asm("tanh.approx.f32 %0, %1;" : "=f"(y) : "f"(x));
    return y;
}

__global__ __launch_bounds__(256) void gather_kernel(
    float* __restrict__ out, int N)
{
    const int head = blockIdx.y;
    const int d = blockIdx.x * 8 + (threadIdx.x >> 5);
    if (d >= N) return;
    const int lane = threadIdx.x & 31;

    const int k   = head * N + d;
    const int beg = g_off[k];
    const int deg = g_cnt[k];

    const __half2* PiRow = (const __half2*)(g_Pd + ((size_t)head * N + d) * 128);
    const float2 zi0 = __half22float2(PiRow[lane * 2]);
    const float2 zi1 = __half22float2(PiRow[lane * 2 + 1]);

    const __half* Qb = g_Q + (size_t)head * N * 256;

    float4 m = make_float4(0.f, 0.f, 0.f, 0.f);

    for (int t = 0; t < deg; t += 8) {
        const int bc = deg - t;          // >=1 in-loop

        // stage 1: 8 independent broadcast src loads (predicated clamp to t)
        int ss[8];
#pragma unroll
        for (int j = 0; j < 8; j++)
            ss[j] = g_srcs[beg + t + ((j < bc) ? j : 0)];

        // stage 2: 8 independent 16B Q gathers, all in flight
        uint4 q[8];
#pragma unroll
        for (int j = 0; j < 8; j++)
            if (j < bc) q[j] = ((const uint4*)(Qb + (size_t)ss[j] * 256))[lane];

        // stage 3: math
#pragma unroll
        for (int j = 0; j < 8; j++) {
            if (j < bc) {
                const float2 zj0 = __half22float2(*(const __half2*)&q[j].x);
                const float2 zj1 = __half22float2(*(const __half2*)&q[j].y);
                const float2 xj0 = __half22float2(*(const __half2*)&q[j].z);
                const float2 xj1 = __half22float2(*(const __half2*)&q[j].w);
                m.x += tanh_ap(zi0.x + zj0.x) * xj0.x;
                m.y += tanh_ap(zi0.y + zj0.y) * xj0.y;
                m.z += tanh_ap(zi1.x + zj1.x) * xj1.x;
                m.w += tanh_ap(zi1.y + zj1.y) * xj1.y;
            }
        }
    }

    *(float4*)(out + (size_t)d * 512 + head * 128 + (lane << 2)) = m;
}

// ---------------------------------------------------------------------------
extern "C" void kernel_launch(void* const* d_in, const int* in_sizes, int n_in,
                              void* d_out, int out_size)
{
    const float* bond = nullptr;   // N*128     = 12,800,000
    const void*  ei   = nullptr;   // 4*2*E     =  4,000,000 (elements)
    const float* W    = nullptr;   // 4*256*128 =    131,072
    const float* b    = nullptr;   // 4*128     =        512

    int N = 0, E = 0;
    for (int i = 0; i < n_in; i++) {
        const int s = in_sizes[i];
        if (s == 4 * 256 * 128)       { W = (const float*)d_in[i]; }
        else if (s == 4 * 128)        { b = (const float*)d_in[i]; }
        else if (s == 4 * 2 * MAXE)   { ei = d_in[i]; E = s / 8; }
        else                          { bond = (const float*)d_in[i]; N = s / BOND_D; }
    }
    float* out = (float*)d_out;
    if (!bond || !ei || !W || !b || N <= 0 || N > MAXN || E <= 0) return;

    const int M = NHEAD * N;

    detect_idx_kernel<<<1, 256>>>((const long long*)ei, N);

    // CSR build
    csr_zero_kernel<<<(M + 255) / 256, 256>>>(M);
    {
        dim3 grid((E + 255) / 256, NHEAD);
        hist_kernel<<<grid, 256>>>(ei, N, E);
    }
    {
        const int nchunks = (M + 1023) / 1024;
        scanA_kernel<<<nchunks, 256>>>(M);
        scanB_kernel<<<1, 512>>>(nchunks);
        scanC_kernel<<<nchunks, 256>>>(M);
    }
    {
        dim3 grid((E + 255) / 256, NHEAD);
        scatter_kernel<<<grid, 256>>>(ei, N, E);
    }

    // fused precompute: Pd (dst side + bias) and Q (src side || fp16 x_j)
    {
        const int GX = 74;                  // 74*8 = 592 = 148 SMs * 4 blocks
        const int smem = SMEM_U32 * 4;      // 52.7 KB -> 4 blocks/SM
        cudaFuncSetAttribute(precompute_kernel,
                             cudaFuncAttributeMaxDynamicSharedMemorySize, smem);
        dim3 grid(GX, 8);
        precompute_kernel<<<grid, 256, smem>>>(bond, W, b, N, GX);
    }

    // dst-major gather: one warp per (head, dst); no atomics, no zero pass.
    {
        dim3 grid((N + 7) / 8, NHEAD);
        gather_kernel<<<grid, 256>>>(out, N);
    }
}

// round 14
// speedup vs baseline: 1.2573x; 1.2573x over previous
#include <cuda_runtime.h>
#include <cuda_fp16.h>
#include <cstdint>

#define BOND_D 128
#define MAXN   100000
#define MAXE   500000
#define NHEAD  4

// Pd[head][n][128] fp16: x@W_top + bias (dst side). 102.4 MB
__device__ __align__(16) __half g_Pd[(size_t)NHEAD * MAXN * BOND_D];
// Q[head][n][256] fp16, quad q: halves [8q..8q+4) = Pj cols 4q..4q+3 (src side),
//                               halves [8q+4..8q+8) = x_j cols 4q..4q+3.
__device__ __align__(16) __half g_Q[(size_t)NHEAD * MAXN * 256];

// CSR scratch (key k = head*N + dst):
__device__ int g_cnt[NHEAD * MAXN];
__device__ int g_off[NHEAD * MAXN];
__device__ int g_cur[NHEAD * MAXN];
__device__ int g_srcs[NHEAD * MAXE];
__device__ int g_part[512];

__device__ int g_idx_is64;

// ---------------------------------------------------------------------------
// Kernel 0: detect edge_index dtype.
// ---------------------------------------------------------------------------
__global__ void detect_idx_kernel(const long long* __restrict__ ei, int N)
{
    __shared__ int bad;
    if (threadIdx.x == 0) bad = 0;
    __syncthreads();
#pragma unroll
    for (int k = 0; k < 4; k++) {
        long long v = ei[threadIdx.x + k * 256];
        if (v < 0 || v >= N) bad = 1;
    }
    __syncthreads();
    if (threadIdx.x == 0) g_idx_is64 = !bad;
}

// ---------------------------------------------------------------------------
// Kernel 1: fused precompute v4 — BOTH halves per head in one block.
//   blockIdx.y = head. 512 threads: warps 0-7 -> half 0 (Pd), 8-15 -> half 1 (Q).
//   One staged bond tile feeds both halves (bond read 4x, not 8x).
// smem (u32): sW[2][128][68] + sBond[32][68] + sP[2][32][68] + bias = 96.3 KB
//   -> 2 blocks/SM (192.5 KB), 32 warps/SM.
// ---------------------------------------------------------------------------
#define SWROW_U32 68
#define SWH_U32  (128 * SWROW_U32)          // one W half
#define SB_U32   (32 * SWROW_U32)
#define SMEM_U32 (2 * SWH_U32 + SB_U32 + 2 * SB_U32 + 128)

__global__ __launch_bounds__(512) void precompute_kernel(
    const float* __restrict__ bond,
    const float* __restrict__ W,
    const float* __restrict__ bias,
    int N, int GX)
{
    extern __shared__ uint32_t smem_u[];
    uint32_t* sWu = smem_u;                     // [2][128][68]
    uint32_t* sBu = sWu + 2 * SWH_U32;          // [32][68]
    uint32_t* sPu = sBu + SB_U32;               // [2][32][68]
    float*  sBias = (float*)(sPu + 2 * SB_U32); // [128]

    const int head = blockIdx.y;
    const int tid  = threadIdx.x;

    // fill both W halves as fp16 (coalesced float4 reads)
    for (int i = tid; i < 2 * 128 * 32; i += 512) {
        const int hw = i >> 12;                    // 0..1  (128*32 = 4096)
        const int r  = (i >> 5) & 127;
        const int c4 = (i & 31) * 4;
        const float* Wg = W + ((size_t)head * 256 + (size_t)hw * 128) * 128;
        const float4 v = *(const float4*)(Wg + (size_t)r * 128 + c4);
        const __half2 h0 = __floats2half2_rn(v.x, v.y);
        const __half2 h1 = __floats2half2_rn(v.z, v.w);
        uint32_t* d = sWu + hw * SWH_U32 + r * SWROW_U32 + (c4 >> 1);
        d[0] = *(const uint32_t*)&h0;
        d[1] = *(const uint32_t*)&h1;
    }
    if (tid < 128) sBias[tid] = bias[head * 128 + tid];

    const int warp = tid >> 5;
    const int lane = tid & 31;
    const int half = warp >> 3;                 // 0: Pd, 1: Q
    const int wl   = warp & 7;
    const int rowgrp = wl >> 2;
    const int colgrp = wl & 3;
    const int gid  = lane >> 2;
    const int tig  = lane & 3;

    const int lr  = lane & 7;
    const int mat = lane >> 3;
    const int a_row  = rowgrp * 16 + lr + ((mat & 1) << 3);
    const int a_kofs = (mat >> 1) << 3;
    const int b_krow = lr + ((mat & 1) << 3);
    const int b_nofs = colgrp * 32 + ((mat >> 1) << 3);

    const uint32_t sB_base = (uint32_t)__cvta_generic_to_shared(sBu);
    const uint32_t sW_base = (uint32_t)__cvta_generic_to_shared(sWu);
    const uint32_t aAddr0 = sB_base + (uint32_t)(a_row * 136 + a_kofs) * 2;
    const uint32_t bAddr0 = sW_base + (uint32_t)half * (SWH_U32 * 4)
                          + (uint32_t)(b_krow * 136 + b_nofs) * 2;

    uint32_t* sPh = sPu + half * SB_U32;

    const int n_tiles = (N + 31) / 32;

    for (int tile = blockIdx.x; tile < n_tiles; tile += GX) {
        __syncthreads();   // previous iteration's sBond/sP readers done

        // stage 32x128 bond tile as fp16 (both halves share it)
        for (int i = tid; i < 32 * 32; i += 512) {
            const int row = i >> 5, c4 = (i & 31) * 4;
            int grow = tile * 32 + row;
            if (grow >= N) grow = N - 1;
            const float4 v = *(const float4*)(bond + (size_t)grow * 128 + c4);
            const __half2 h0 = __floats2half2_rn(v.x, v.y);
            const __half2 h1 = __floats2half2_rn(v.z, v.w);
            uint32_t* d = sBu + row * SWROW_U32 + (c4 >> 1);
            d[0] = *(const uint32_t*)&h0;
            d[1] = *(const uint32_t*)&h1;
        }
        __syncthreads();   // also orders the one-time W fill before first MMA

        float acc[4][4];
#pragma unroll
        for (int nc = 0; nc < 4; nc++) {
            acc[nc][0] = 0.f; acc[nc][1] = 0.f; acc[nc][2] = 0.f; acc[nc][3] = 0.f;
        }

#pragma unroll
        for (int kc = 0; kc < 8; kc++) {
            uint32_t a0, a1, a2, a3;
            asm volatile(
                "ldmatrix.sync.aligned.m8n8.x4.shared.b16 {%0,%1,%2,%3}, [%4];"
                : "=r"(a0), "=r"(a1), "=r"(a2), "=r"(a3)
                : "r"(aAddr0 + kc * 32));
#pragma unroll
            for (int pair = 0; pair < 2; pair++) {
                uint32_t b0, b1, b2, b3;
                asm volatile(
                    "ldmatrix.sync.aligned.m8n8.x4.trans.shared.b16 "
                    "{%0,%1,%2,%3}, [%4];"
                    : "=r"(b0), "=r"(b1), "=r"(b2), "=r"(b3)
                    : "r"(bAddr0 + pair * 32 + kc * 16 * 272));
                const int nc = pair * 2;
                asm volatile(
                    "mma.sync.aligned.m16n8k16.row.col.f32.f16.f16.f32 "
                    "{%0,%1,%2,%3}, {%4,%5,%6,%7}, {%8,%9}, {%0,%1,%2,%3};"
                    : "+f"(acc[nc][0]), "+f"(acc[nc][1]),
                      "+f"(acc[nc][2]), "+f"(acc[nc][3])
                    : "r"(a0), "r"(a1), "r"(a2), "r"(a3), "r"(b0), "r"(b1));
                asm volatile(
                    "mma.sync.aligned.m16n8k16.row.col.f32.f16.f16.f32 "
                    "{%0,%1,%2,%3}, {%4,%5,%6,%7}, {%8,%9}, {%0,%1,%2,%3};"
                    : "+f"(acc[nc + 1][0]), "+f"(acc[nc + 1][1]),
                      "+f"(acc[nc + 1][2]), "+f"(acc[nc + 1][3])
                    : "r"(a0), "r"(a1), "r"(a2), "r"(a3), "r"(b2), "r"(b3));
            }
        }

        const int tr0 = rowgrp * 16 + gid;
        const int tr1 = tr0 + 8;
#pragma unroll
        for (int nc = 0; nc < 4; nc++) {
            const int c0 = colgrp * 32 + nc * 8 + tig * 2;
            float bx = 0.f, by = 0.f;
            if (half == 0) { bx = sBias[c0]; by = sBias[c0 + 1]; }
            const __half2 h0 = __floats2half2_rn(acc[nc][0] + bx, acc[nc][1] + by);
            const __half2 h1 = __floats2half2_rn(acc[nc][2] + bx, acc[nc][3] + by);
            sPh[tr0 * SWROW_U32 + (c0 >> 1)] = *(const uint32_t*)&h0;
            sPh[tr1 * SWROW_U32 + (c0 >> 1)] = *(const uint32_t*)&h1;
        }
        __syncthreads();

        // coalesced 16B stores; group A (tid<256) -> Pd, group B -> Q
        if (half == 0) {
            __half* Pg = g_Pd + (size_t)head * N * 128;
            const uint32_t* sPa = sPu;              // half-0 staging
#pragma unroll
            for (int it = 0; it < 2; it++) {
                const int idx = tid + it * 256;     // tid in [0,256)
                const int row = idx >> 4, g8 = idx & 15;
                const int grow = tile * 32 + row;
                if (grow < N) {
                    const uint32_t* p = sPa + row * SWROW_U32 + g8 * 4;
                    uint4 v; v.x = p[0]; v.y = p[1]; v.z = p[2]; v.w = p[3];
                    *(uint4*)(Pg + (size_t)grow * 128 + g8 * 8) = v;
                }
            }
        } else {
            __half* Qg = g_Q + (size_t)head * N * 256;
            const uint32_t* sPb = sPu + SB_U32;     // half-1 staging
            const int gt = tid - 256;               // [0,256)
#pragma unroll
            for (int it = 0; it < 4; it++) {
                const int idx = gt + it * 256;
                const int row = idx >> 5, q = idx & 31;
                const int grow = tile * 32 + row;
                if (grow < N) {
                    const uint32_t* p = sPb + row * SWROW_U32 + q * 2;
                    const uint32_t* x = sBu + row * SWROW_U32 + q * 2;
                    uint4 v;
                    v.x = p[0]; v.y = p[1];
                    v.z = x[0]; v.w = x[1];
                    *(uint4*)(Qg + (size_t)grow * 256 + q * 8) = v;
                }
            }
        }
    }
}

// ---------------------------------------------------------------------------
// CSR build kernels (unchanged)
// ---------------------------------------------------------------------------
__global__ void csr_zero_kernel(int M)
{
    const int i = blockIdx.x * blockDim.x + threadIdx.x;
    if (i < M) { g_cnt[i] = 0; g_cur[i] = 0; }
}

__global__ void hist_kernel(const void* __restrict__ ei_raw, int N, int E)
{
    const int e = blockIdx.x * blockDim.x + threadIdx.x;
    const int head = blockIdx.y;
    if (e >= E) return;
    int dst;
    if (g_idx_is64) dst = (int)((const long long*)ei_raw)[(size_t)head * 2 * E + E + e];
    else            dst = ((const int*)ei_raw)[(size_t)head * 2 * E + E + e];
    dst = min(max(dst, 0), N - 1);
    atomicAdd(&g_cnt[head * N + dst], 1);
}

__global__ void scanA_kernel(int M)
{
    __shared__ int sh[256];
    const int tid = threadIdx.x;
    const int base = blockIdx.x * 1024 + tid * 4;
    int s = 0;
#pragma unroll
    for (int k = 0; k < 4; k++) if (base + k < M) s += g_cnt[base + k];
    sh[tid] = s; __syncthreads();
    for (int o = 128; o > 0; o >>= 1) {
        if (tid < o) sh[tid] += sh[tid + o];
        __syncthreads();
    }
    if (tid == 0) g_part[blockIdx.x] = sh[0];
}

__global__ void scanB_kernel(int P)
{
    __shared__ int sh[512];
    const int tid = threadIdx.x;
    const int v = (tid < P) ? g_part[tid] : 0;
    sh[tid] = v; __syncthreads();
    for (int o = 1; o < 512; o <<= 1) {
        const int t = (tid >= o) ? sh[tid - o] : 0;
        __syncthreads();
        sh[tid] += t;
        __syncthreads();
    }
    if (tid < P) g_part[tid] = sh[tid] - v;
}

__global__ void scanC_kernel(int M)
{
    __shared__ int sh[256];
    const int tid = threadIdx.x;
    const int base = blockIdx.x * 1024 + tid * 4;
    int v[4], e[4], s = 0;
#pragma unroll
    for (int k = 0; k < 4; k++) v[k] = (base + k < M) ? g_cnt[base + k] : 0;
#pragma unroll
    for (int k = 0; k < 4; k++) { e[k] = s; s += v[k]; }
    sh[tid] = s; __syncthreads();
    const int mine = s;
    for (int o = 1; o < 256; o <<= 1) {
        const int t = (tid >= o) ? sh[tid - o] : 0;
        __syncthreads();
        sh[tid] += t;
        __syncthreads();
    }
    const int pre = g_part[blockIdx.x] + sh[tid] - mine;
#pragma unroll
    for (int k = 0; k < 4; k++) if (base + k < M) g_off[base + k] = pre + e[k];
}

__global__ void scatter_kernel(const void* __restrict__ ei_raw, int N, int E)
{
    const int e = blockIdx.x * blockDim.x + threadIdx.x;
    const int head = blockIdx.y;
    if (e >= E) return;
    int src, dst;
    if (g_idx_is64) {
        const long long* eh = (const long long*)ei_raw + (size_t)head * 2 * E;
        src = (int)eh[e];
        dst = (int)eh[E + e];
    } else {
        const int* eh = (const int*)ei_raw + (size_t)head * 2 * E;
        src = eh[e];
        dst = eh[E + e];
    }
    src = min(max(src, 0), N - 1);
    dst = min(max(dst, 0), N - 1);
    const int k = head * N + dst;
    const int pos = g_off[k] + atomicAdd(&g_cur[k], 1);
    g_srcs[pos] = src;
}

// ---------------------------------------------------------------------------
// Kernel 3: dst-major gather — R12's proven 4-wide shape + cross-iteration
// src prefetch (sn[4], +4 regs; q stays 4-wide to protect occupancy).
// ---------------------------------------------------------------------------
__device__ __forceinline__ float tanh_ap(float x)
{
    float y;
    asm("tanh.approx.f32 %0, %1;" : "=f"(y) : "f"(x));
    return y;
}

__global__ __launch_bounds__(256) void gather_kernel(
    float* __restrict__ out, int N)
{
    const int head = blockIdx.y;
    const int d = blockIdx.x * 8 + (threadIdx.x >> 5);
    if (d >= N) return;
    const int lane = threadIdx.x & 31;

    const int k   = head * N + d;
    const int beg = g_off[k];
    const int deg = g_cnt[k];

    const __half2* PiRow = (const __half2*)(g_Pd + ((size_t)head * N + d) * 128);
    const float2 zi0 = __half22float2(PiRow[lane * 2]);
    const float2 zi1 = __half22float2(PiRow[lane * 2 + 1]);

    const __half* Qb = g_Q + (size_t)head * N * 256;

    float4 m = make_float4(0.f, 0.f, 0.f, 0.f);

    if (deg > 0) {
        int ss[4];
#pragma unroll
        for (int j = 0; j < 4; j++)
            ss[j] = g_srcs[beg + ((j < deg) ? j : 0)];

        for (int t = 0; t < deg; t += 4) {
            const int bc = deg - t;

            uint4 q[4];
#pragma unroll
            for (int j = 0; j < 4; j++)
                if (j < bc) q[j] = ((const uint4*)(Qb + (size_t)ss[j] * 256))[lane];

            // prefetch next chunk's srcs while q loads are in flight
            const int nb = deg - (t + 4);
            int sn[4];
#pragma unroll
            for (int j = 0; j < 4; j++)
                sn[j] = (nb > 0) ? g_srcs[beg + t + 4 + ((j < nb) ? j : 0)] : 0;

#pragma unroll
            for (int j = 0; j < 4; j++) {
                if (j < bc) {
                    const float2 zj0 = __half22float2(*(const __half2*)&q[j].x);
                    const float2 zj1 = __half22float2(*(const __half2*)&q[j].y);
                    const float2 xj0 = __half22float2(*(const __half2*)&q[j].z);
                    const float2 xj1 = __half22float2(*(const __half2*)&q[j].w);
                    m.x += tanh_ap(zi0.x + zj0.x) * xj0.x;
                    m.y += tanh_ap(zi0.y + zj0.y) * xj0.y;
                    m.z += tanh_ap(zi1.x + zj1.x) * xj1.x;
                    m.w += tanh_ap(zi1.y + zj1.y) * xj1.y;
                }
            }
#pragma unroll
            for (int j = 0; j < 4; j++) ss[j] = sn[j];
        }
    }

    *(float4*)(out + (size_t)d * 512 + head * 128 + (lane << 2)) = m;
}

// ---------------------------------------------------------------------------
extern "C" void kernel_launch(void* const* d_in, const int* in_sizes, int n_in,
                              void* d_out, int out_size)
{
    const float* bond = nullptr;
    const void*  ei   = nullptr;
    const float* W    = nullptr;
    const float* b    = nullptr;

    int N = 0, E = 0;
    for (int i = 0; i < n_in; i++) {
        const int s = in_sizes[i];
        if (s == 4 * 256 * 128)       { W = (const float*)d_in[i]; }
        else if (s == 4 * 128)        { b = (const float*)d_in[i]; }
        else if (s == 4 * 2 * MAXE)   { ei = d_in[i]; E = s / 8; }
        else                          { bond = (const float*)d_in[i]; N = s / BOND_D; }
    }
    float* out = (float*)d_out;
    if (!bond || !ei || !W || !b || N <= 0 || N > MAXN || E <= 0) return;

    const int M = NHEAD * N;

    detect_idx_kernel<<<1, 256>>>((const long long*)ei, N);

    // CSR build
    csr_zero_kernel<<<(M + 255) / 256, 256>>>(M);
    {
        dim3 grid((E + 255) / 256, NHEAD);
        hist_kernel<<<grid, 256>>>(ei, N, E);
    }
    {
        const int nchunks = (M + 1023) / 1024;
        scanA_kernel<<<nchunks, 256>>>(M);
        scanB_kernel<<<1, 512>>>(nchunks);
        scanC_kernel<<<nchunks, 256>>>(M);
    }
    {
        dim3 grid((E + 255) / 256, NHEAD);
        scatter_kernel<<<grid, 256>>>(ei, N, E);
    }

    // fused precompute: both halves per head, one bond staging
    {
        const int GX = 74;                  // 74*4 = 296 = 148 SMs * 2 blocks
        const int smem = SMEM_U32 * 4;      // 96.3 KB -> 2 blocks/SM
        cudaFuncSetAttribute(precompute_kernel,
                             cudaFuncAttributeMaxDynamicSharedMemorySize, smem);
        dim3 grid(GX, NHEAD);
        precompute_kernel<<<grid, 512, smem>>>(bond, W, b, N, GX);
    }

    // dst-major gather (4-wide + src prefetch)
    {
        dim3 grid((N + 7) / 8, NHEAD);
        gather_kernel<<<grid, 256>>>(out, N);
    }
}

// round 15
// speedup vs baseline: 1.4153x; 1.1257x over previous
#include <cuda_runtime.h>
#include <cuda_fp16.h>
#include <cstdint>

#define BOND_D 128
#define MAXN   100000
#define MAXE   500000
#define NHEAD  4

// Pd[head][n][128] fp16: x@W_top + bias (dst side). 102.4 MB
__device__ __align__(16) __half g_Pd[(size_t)NHEAD * MAXN * BOND_D];
// Pj[head][n][128] fp16: x@W_bot (src side). 102.4 MB
__device__ __align__(16) __half g_Pj[(size_t)NHEAD * MAXN * BOND_D];
// X[n][128] fp16: bond rounded to fp16, shared across heads. 25.6 MB
__device__ __align__(16) __half g_X[(size_t)MAXN * BOND_D];

// CSR scratch (key k = head*N + dst):
__device__ int g_cnt[NHEAD * MAXN];
__device__ int g_off[NHEAD * MAXN];
__device__ int g_cur[NHEAD * MAXN];
__device__ int g_srcs[NHEAD * MAXE];
__device__ int g_part[512];

__device__ int g_idx_is64;

// ---------------------------------------------------------------------------
// Kernel 0: detect edge_index dtype. int64 indices in [0,N) all pass; int32
// data read as int64 = lo + hi*2^32 fails immediately. Deterministic.
// ---------------------------------------------------------------------------
__global__ void detect_idx_kernel(const long long* __restrict__ ei, int N)
{
    __shared__ int bad;
    if (threadIdx.x == 0) bad = 0;
    __syncthreads();
#pragma unroll
    for (int k = 0; k < 4; k++) {
        long long v = ei[threadIdx.x + k * 256];
        if (v < 0 || v >= N) bad = 1;
    }
    __syncthreads();
    if (threadIdx.x == 0) g_idx_is64 = !bad;
}

// ---------------------------------------------------------------------------
// Kernel 1: fused precompute (R12 shape: 256 thr, g = head*2+half, 4 blk/SM).
//   half 0: Pd[head] = bond @ W[head][0:128] + bias
//   half 1: Pj[head] = bond @ W[head][128:256];  g==1 also writes X = fp16(bond)
// ---------------------------------------------------------------------------
#define SWROW_U32 68
#define SW_U32   (128 * SWROW_U32)
#define SB_U32   (32 * SWROW_U32)
#define SP_U32   (32 * SWROW_U32)
#define SMEM_U32 (SW_U32 + SB_U32 + SP_U32 + 128)

__global__ __launch_bounds__(256) void precompute_kernel(
    const float* __restrict__ bond,
    const float* __restrict__ W,
    const float* __restrict__ bias,
    int N, int GX)
{
    extern __shared__ uint32_t smem_u[];
    uint32_t* sWu = smem_u;                 // [128][68] half2
    uint32_t* sBu = sWu + SW_U32;           // [32][68]  half2
    uint32_t* sPu = sBu + SB_U32;           // [32][68]  half2
    float*  sBias = (float*)(sPu + SP_U32); // [128]

    const int g    = blockIdx.y;
    const int head = g >> 1;
    const int half = g & 1;
    const float* Wg = W + ((size_t)head * 256 + (size_t)half * 128) * 128;

    for (int i = threadIdx.x; i < 128 * 32; i += blockDim.x) {
        const int row = i >> 5, c4 = (i & 31) * 4;
        const float4 v = *(const float4*)(Wg + (size_t)row * 128 + c4);
        const __half2 h0 = __floats2half2_rn(v.x, v.y);
        const __half2 h1 = __floats2half2_rn(v.z, v.w);
        uint32_t* d = sWu + row * SWROW_U32 + (c4 >> 1);
        d[0] = *(const uint32_t*)&h0;
        d[1] = *(const uint32_t*)&h1;
    }
    if (threadIdx.x < 128) sBias[threadIdx.x] = bias[head * 128 + threadIdx.x];

    const int warp   = threadIdx.x >> 5;
    const int lane   = threadIdx.x & 31;
    const int rowgrp = warp >> 2;
    const int colgrp = warp & 3;
    const int gid  = lane >> 2;
    const int tig  = lane & 3;

    const int lr  = lane & 7;
    const int mat = lane >> 3;
    const int a_row  = rowgrp * 16 + lr + ((mat & 1) << 3);
    const int a_kofs = (mat >> 1) << 3;
    const int b_krow = lr + ((mat & 1) << 3);
    const int b_nofs = colgrp * 32 + ((mat >> 1) << 3);

    const uint32_t sB_base = (uint32_t)__cvta_generic_to_shared(sBu);
    const uint32_t sW_base = (uint32_t)__cvta_generic_to_shared(sWu);
    const uint32_t aAddr0 = sB_base + (uint32_t)(a_row * 136 + a_kofs) * 2;
    const uint32_t bAddr0 = sW_base + (uint32_t)(b_krow * 136 + b_nofs) * 2;

    const int n_tiles = (N + 31) / 32;

    for (int tile = blockIdx.x; tile < n_tiles; tile += GX) {
        __syncthreads();

        for (int i = threadIdx.x; i < 32 * 32; i += blockDim.x) {
            const int row = i >> 5, c4 = (i & 31) * 4;
            int grow = tile * 32 + row;
            if (grow >= N) grow = N - 1;
            const float4 v = *(const float4*)(bond + (size_t)grow * 128 + c4);
            const __half2 h0 = __floats2half2_rn(v.x, v.y);
            const __half2 h1 = __floats2half2_rn(v.z, v.w);
            uint32_t* d = sBu + row * SWROW_U32 + (c4 >> 1);
            d[0] = *(const uint32_t*)&h0;
            d[1] = *(const uint32_t*)&h1;
        }
        __syncthreads();

        float acc[4][4];
#pragma unroll
        for (int nc = 0; nc < 4; nc++) {
            acc[nc][0] = 0.f; acc[nc][1] = 0.f; acc[nc][2] = 0.f; acc[nc][3] = 0.f;
        }

#pragma unroll
        for (int kc = 0; kc < 8; kc++) {
            uint32_t a0, a1, a2, a3;
            asm volatile(
                "ldmatrix.sync.aligned.m8n8.x4.shared.b16 {%0,%1,%2,%3}, [%4];"
                : "=r"(a0), "=r"(a1), "=r"(a2), "=r"(a3)
                : "r"(aAddr0 + kc * 32));
#pragma unroll
            for (int pair = 0; pair < 2; pair++) {
                uint32_t b0, b1, b2, b3;
                asm volatile(
                    "ldmatrix.sync.aligned.m8n8.x4.trans.shared.b16 "
                    "{%0,%1,%2,%3}, [%4];"
                    : "=r"(b0), "=r"(b1), "=r"(b2), "=r"(b3)
                    : "r"(bAddr0 + pair * 32 + kc * 16 * 272));
                const int nc = pair * 2;
                asm volatile(
                    "mma.sync.aligned.m16n8k16.row.col.f32.f16.f16.f32 "
                    "{%0,%1,%2,%3}, {%4,%5,%6,%7}, {%8,%9}, {%0,%1,%2,%3};"
                    : "+f"(acc[nc][0]), "+f"(acc[nc][1]),
                      "+f"(acc[nc][2]), "+f"(acc[nc][3])
                    : "r"(a0), "r"(a1), "r"(a2), "r"(a3), "r"(b0), "r"(b1));
                asm volatile(
                    "mma.sync.aligned.m16n8k16.row.col.f32.f16.f16.f32 "
                    "{%0,%1,%2,%3}, {%4,%5,%6,%7}, {%8,%9}, {%0,%1,%2,%3};"
                    : "+f"(acc[nc + 1][0]), "+f"(acc[nc + 1][1]),
                      "+f"(acc[nc + 1][2]), "+f"(acc[nc + 1][3])
                    : "r"(a0), "r"(a1), "r"(a2), "r"(a3), "r"(b2), "r"(b3));
            }
        }

        const int tr0 = rowgrp * 16 + gid;
        const int tr1 = tr0 + 8;
#pragma unroll
        for (int nc = 0; nc < 4; nc++) {
            const int c0 = colgrp * 32 + nc * 8 + tig * 2;
            float bx = 0.f, by = 0.f;
            if (half == 0) { bx = sBias[c0]; by = sBias[c0 + 1]; }
            const __half2 h0 = __floats2half2_rn(acc[nc][0] + bx, acc[nc][1] + by);
            const __half2 h1 = __floats2half2_rn(acc[nc][2] + bx, acc[nc][3] + by);
            sPu[tr0 * SWROW_U32 + (c0 >> 1)] = *(const uint32_t*)&h0;
            sPu[tr1 * SWROW_U32 + (c0 >> 1)] = *(const uint32_t*)&h1;
        }
        __syncthreads();

        // coalesced 16B global stores: [32][128] halves = 512 uint4 chunks
        __half* Pg = (half == 0 ? g_Pd : g_Pj) + (size_t)head * N * 128;
#pragma unroll
        for (int it = 0; it < 2; it++) {
            const int idx = threadIdx.x + it * 256;
            const int row = idx >> 4, g8 = idx & 15;
            const int grow = tile * 32 + row;
            if (grow < N) {
                const uint32_t* p = sPu + row * SWROW_U32 + g8 * 4;
                uint4 v; v.x = p[0]; v.y = p[1]; v.z = p[2]; v.w = p[3];
                *(uint4*)(Pg + (size_t)grow * 128 + g8 * 8) = v;
            }
        }
        if (g == 1) {   // one block column also writes the shared X = fp16(bond)
#pragma unroll
            for (int it = 0; it < 2; it++) {
                const int idx = threadIdx.x + it * 256;
                const int row = idx >> 4, g8 = idx & 15;
                const int grow = tile * 32 + row;
                if (grow < N) {
                    const uint32_t* x = sBu + row * SWROW_U32 + g8 * 4;
                    uint4 v; v.x = x[0]; v.y = x[1]; v.z = x[2]; v.w = x[3];
                    *(uint4*)(g_X + (size_t)grow * 128 + g8 * 8) = v;
                }
            }
        }
    }
}

// ---------------------------------------------------------------------------
// CSR build kernels (unchanged from R12)
// ---------------------------------------------------------------------------
__global__ void csr_zero_kernel(int M)
{
    const int i = blockIdx.x * blockDim.x + threadIdx.x;
    if (i < M) { g_cnt[i] = 0; g_cur[i] = 0; }
}

__global__ void hist_kernel(const void* __restrict__ ei_raw, int N, int E)
{
    const int e = blockIdx.x * blockDim.x + threadIdx.x;
    const int head = blockIdx.y;
    if (e >= E) return;
    int dst;
    if (g_idx_is64) dst = (int)((const long long*)ei_raw)[(size_t)head * 2 * E + E + e];
    else            dst = ((const int*)ei_raw)[(size_t)head * 2 * E + E + e];
    dst = min(max(dst, 0), N - 1);
    atomicAdd(&g_cnt[head * N + dst], 1);
}

__global__ void scanA_kernel(int M)
{
    __shared__ int sh[256];
    const int tid = threadIdx.x;
    const int base = blockIdx.x * 1024 + tid * 4;
    int s = 0;
#pragma unroll
    for (int k = 0; k < 4; k++) if (base + k < M) s += g_cnt[base + k];
    sh[tid] = s; __syncthreads();
    for (int o = 128; o > 0; o >>= 1) {
        if (tid < o) sh[tid] += sh[tid + o];
        __syncthreads();
    }
    if (tid == 0) g_part[blockIdx.x] = sh[0];
}

__global__ void scanB_kernel(int P)
{
    __shared__ int sh[512];
    const int tid = threadIdx.x;
    const int v = (tid < P) ? g_part[tid] : 0;
    sh[tid] = v; __syncthreads();
    for (int o = 1; o < 512; o <<= 1) {
        const int t = (tid >= o) ? sh[tid - o] : 0;
        __syncthreads();
        sh[tid] += t;
        __syncthreads();
    }
    if (tid < P) g_part[tid] = sh[tid] - v;
}

__global__ void scanC_kernel(int M)
{
    __shared__ int sh[256];
    const int tid = threadIdx.x;
    const int base = blockIdx.x * 1024 + tid * 4;
    int v[4], e[4], s = 0;
#pragma unroll
    for (int k = 0; k < 4; k++) v[k] = (base + k < M) ? g_cnt[base + k] : 0;
#pragma unroll
    for (int k = 0; k < 4; k++) { e[k] = s; s += v[k]; }
    sh[tid] = s; __syncthreads();
    const int mine = s;
    for (int o = 1; o < 256; o <<= 1) {
        const int t = (tid >= o) ? sh[tid - o] : 0;
        __syncthreads();
        sh[tid] += t;
        __syncthreads();
    }
    const int pre = g_part[blockIdx.x] + sh[tid] - mine;
#pragma unroll
    for (int k = 0; k < 4; k++) if (base + k < M) g_off[base + k] = pre + e[k];
}

__global__ void scatter_kernel(const void* __restrict__ ei_raw, int N, int E)
{
    const int e = blockIdx.x * blockDim.x + threadIdx.x;
    const int head = blockIdx.y;
    if (e >= E) return;
    int src, dst;
    if (g_idx_is64) {
        const long long* eh = (const long long*)ei_raw + (size_t)head * 2 * E;
        src = (int)eh[e];
        dst = (int)eh[E + e];
    } else {
        const int* eh = (const int*)ei_raw + (size_t)head * 2 * E;
        src = eh[e];
        dst = eh[E + e];
    }
    src = min(max(src, 0), N - 1);
    dst = min(max(dst, 0), N - 1);
    const int k = head * N + dst;
    const int pos = g_off[k] + atomicAdd(&g_cur[k], 1);
    g_srcs[pos] = src;
}

// ---------------------------------------------------------------------------
// Kernel 3: dst-major gather — exact R12 loop shape; per edge loads split
// into Pj (head-private) + X (shared, L2-resident). Streaming hints on the
// read-once (Pi) and write-once (out) paths keep L2 for Pj+X.
// ---------------------------------------------------------------------------
__device__ __forceinline__ float tanh_ap(float x)
{
    float y;
    asm("tanh.approx.f32 %0, %1;" : "=f"(y) : "f"(x));
    return y;
}

__global__ __launch_bounds__(256) void gather_kernel(
    float* __restrict__ out, int N)
{
    const int head = blockIdx.y;
    const int d = blockIdx.x * 8 + (threadIdx.x >> 5);
    if (d >= N) return;
    const int lane = threadIdx.x & 31;

    const int k   = head * N + d;
    const int beg = g_off[k];
    const int deg = g_cnt[k];

    const uint2 piw = __ldcs(
        (const uint2*)(g_Pd + ((size_t)head * N + d) * 128) + lane);
    const float2 zi0 = __half22float2(*(const __half2*)&piw.x);
    const float2 zi1 = __half22float2(*(const __half2*)&piw.y);

    const __half* Pjb = g_Pj + (size_t)head * N * 128;

    float4 m = make_float4(0.f, 0.f, 0.f, 0.f);

    for (int t = 0; t < deg; t += 4) {
        const int bc = deg - t;
        const int s0 = g_srcs[beg + t];
        const int s1 = bc > 1 ? g_srcs[beg + t + 1] : s0;
        const int s2 = bc > 2 ? g_srcs[beg + t + 2] : s0;
        const int s3 = bc > 3 ? g_srcs[beg + t + 3] : s0;

        const uint2 p0 = ((const uint2*)(Pjb + (size_t)s0 * 128))[lane];
        const uint2 p1 = ((const uint2*)(Pjb + (size_t)s1 * 128))[lane];
        const uint2 p2 = ((const uint2*)(Pjb + (size_t)s2 * 128))[lane];
        const uint2 p3 = ((const uint2*)(Pjb + (size_t)s3 * 128))[lane];
        const uint2 x0 = ((const uint2*)(g_X + (size_t)s0 * 128))[lane];
        const uint2 x1 = ((const uint2*)(g_X + (size_t)s1 * 128))[lane];
        const uint2 x2 = ((const uint2*)(g_X + (size_t)s2 * 128))[lane];
        const uint2 x3 = ((const uint2*)(g_X + (size_t)s3 * 128))[lane];

        {
            const float2 zj0 = __half22float2(*(const __half2*)&p0.x);
            const float2 zj1 = __half22float2(*(const __half2*)&p0.y);
            const float2 xj0 = __half22float2(*(const __half2*)&x0.x);
            const float2 xj1 = __half22float2(*(const __half2*)&x0.y);
            m.x += tanh_ap(zi0.x + zj0.x) * xj0.x;
            m.y += tanh_ap(zi0.y + zj0.y) * xj0.y;
            m.z += tanh_ap(zi1.x + zj1.x) * xj1.x;
            m.w += tanh_ap(zi1.y + zj1.y) * xj1.y;
        }
        if (bc > 1) {
            const float2 zj0 = __half22float2(*(const __half2*)&p1.x);
            const float2 zj1 = __half22float2(*(const __half2*)&p1.y);
            const float2 xj0 = __half22float2(*(const __half2*)&x1.x);
            const float2 xj1 = __half22float2(*(const __half2*)&x1.y);
            m.x += tanh_ap(zi0.x + zj0.x) * xj0.x;
            m.y += tanh_ap(zi0.y + zj0.y) * xj0.y;
            m.z += tanh_ap(zi1.x + zj1.x) * xj1.x;
            m.w += tanh_ap(zi1.y + zj1.y) * xj1.y;
        }
        if (bc > 2) {
            const float2 zj0 = __half22float2(*(const __half2*)&p2.x);
            const float2 zj1 = __half22float2(*(const __half2*)&p2.y);
            const float2 xj0 = __half22float2(*(const __half2*)&x2.x);
            const float2 xj1 = __half22float2(*(const __half2*)&x2.y);
            m.x += tanh_ap(zi0.x + zj0.x) * xj0.x;
            m.y += tanh_ap(zi0.y + zj0.y) * xj0.y;
            m.z += tanh_ap(zi1.x + zj1.x) * xj1.x;
            m.w += tanh_ap(zi1.y + zj1.y) * xj1.y;
        }
        if (bc > 3) {
            const float2 zj0 = __half22float2(*(const __half2*)&p3.x);
            const float2 zj1 = __half22float2(*(const __half2*)&p3.y);
            const float2 xj0 = __half22float2(*(const __half2*)&x3.x);
            const float2 xj1 = __half22float2(*(const __half2*)&x3.y);
            m.x += tanh_ap(zi0.x + zj0.x) * xj0.x;
            m.y += tanh_ap(zi0.y + zj0.y) * xj0.y;
            m.z += tanh_ap(zi1.x + zj1.x) * xj1.x;
            m.w += tanh_ap(zi1.y + zj1.y) * xj1.y;
        }
    }

    __stcs((float4*)(out + (size_t)d * 512 + head * 128 + (lane << 2)), m);
}

// ---------------------------------------------------------------------------
extern "C" void kernel_launch(void* const* d_in, const int* in_sizes, int n_in,
                              void* d_out, int out_size)
{
    const float* bond = nullptr;
    const void*  ei   = nullptr;
    const float* W    = nullptr;
    const float* b    = nullptr;

    int N = 0, E = 0;
    for (int i = 0; i < n_in; i++) {
        const int s = in_sizes[i];
        if (s == 4 * 256 * 128)       { W = (const float*)d_in[i]; }
        else if (s == 4 * 128)        { b = (const float*)d_in[i]; }
        else if (s == 4 * 2 * MAXE)   { ei = d_in[i]; E = s / 8; }
        else                          { bond = (const float*)d_in[i]; N = s / BOND_D; }
    }
    float* out = (float*)d_out;
    if (!bond || !ei || !W || !b || N <= 0 || N > MAXN || E <= 0) return;

    const int M = NHEAD * N;

    detect_idx_kernel<<<1, 256>>>((const long long*)ei, N);

    // CSR build
    csr_zero_kernel<<<(M + 255) / 256, 256>>>(M);
    {
        dim3 grid((E + 255) / 256, NHEAD);
        hist_kernel<<<grid, 256>>>(ei, N, E);
    }
    {
        const int nchunks = (M + 1023) / 1024;
        scanA_kernel<<<nchunks, 256>>>(M);
        scanB_kernel<<<1, 512>>>(nchunks);
        scanC_kernel<<<nchunks, 256>>>(M);
    }
    {
        dim3 grid((E + 255) / 256, NHEAD);
        scatter_kernel<<<grid, 256>>>(ei, N, E);
    }

    // fused precompute (R12 shape): Pd, Pj, and shared X
    {
        const int GX = 74;                  // 74*8 = 592 = 148 SMs * 4 blocks
        const int smem = SMEM_U32 * 4;      // 52.7 KB -> 4 blocks/SM
        cudaFuncSetAttribute(precompute_kernel,
                             cudaFuncAttributeMaxDynamicSharedMemorySize, smem);
        dim3 grid(GX, 8);
        precompute_kernel<<<grid, 256, smem>>>(bond, W, b, N, GX);
    }

    // dst-major gather (R12 loop shape, split Pj/X loads)
    {
        dim3 grid((N + 7) / 8, NHEAD);
        gather_kernel<<<grid, 256>>>(out, N);
    }
}